// round 4
// baseline (speedup 1.0000x reference)
#include <cuda_runtime.h>
#include <cstdint>

// CIC deposition: 10M particles -> 256^3 float grid.
// Round 4: 2-pass slab deposition. Pass p deposits only particles whose cell
// cx is in slab p (cx>>7 == p), keeping that 32MB grid slab L2-resident so
// atomic RMWs stop thrashing to DRAM. Keeps round-2 v4-RED z-pair scheme and
// round-3 float4 streaming loads.

static constexpr int   NC    = 256;
static constexpr float GMINF = -10.0f;
static constexpr float DXF   = (float)(20.0 / 255.0);

__global__ void zero_grid_kernel(float4* __restrict__ out, int n4) {
    int i = blockIdx.x * blockDim.x + threadIdx.x;
    if (i < n4) out[i] = make_float4(0.f, 0.f, 0.f, 0.f);
}

__device__ __forceinline__ void red_v4p(float* p, float a, float b, float c, float d, int pred) {
    asm volatile(
        "{\n\t"
        ".reg .pred q;\n\t"
        "setp.ne.s32 q, %5, 0;\n\t"
        "@q red.global.add.v4.f32 [%0], {%1, %2, %3, %4};\n\t"
        "}"
        :: "l"(p), "f"(a), "f"(b), "f"(c), "f"(d), "r"(pred) : "memory");
}

__device__ __forceinline__ void red_v1p(float* p, float a, int pred) {
    asm volatile(
        "{\n\t"
        ".reg .pred q;\n\t"
        "setp.ne.s32 q, %2, 0;\n\t"
        "@q red.global.add.f32 [%0], %1;\n\t"
        "}"
        :: "l"(p), "f"(a), "r"(pred) : "memory");
}

__device__ __forceinline__ void deposit_one(
    float px, float py, float pz, float w, float* __restrict__ grid, int pass)
{
    // Match JAX float32 arithmetic: subtract then IEEE divide
    float fx = (px - GMINF) / DXF;
    float fy = (py - GMINF) / DXF;
    float fz = (pz - GMINF) / DXF;

    float ix = floorf(fx), iy = floorf(fy), iz = floorf(fz);
    int cx = (int)ix, cy = (int)iy, cz = (int)iz;

    if ((unsigned)cx > 255u || (unsigned)cy > 255u || (unsigned)cz > 255u) return;
    if ((cx >> 7) != pass) return;   // slab ownership

    float ox = fx - ix, oy = fy - iy, oz = fz - iz;

    float wx0 = w * (1.0f - ox);
    float wx1 = w * ox;
    float y0 = 1.0f - oy, y1 = oy;
    float z0 = 1.0f - oz, z1 = oz;

    bool bx = cx < (NC - 1);
    bool by = cy < (NC - 1);

    int  m    = cz & 3;
    int  use4 = (m != 3);
    int  fb   = !use4;
    int  fb2  = fb & (cz < (NC - 1));
    float a0 = (m == 0) ? 1.0f : 0.0f;
    float a1 = (m == 1) ? 1.0f : 0.0f;
    float a2 = (m == 2) ? 1.0f : 0.0f;

    float* g  = grid + (((size_t)cx * NC + (size_t)cy) * NC + (size_t)cz);
    float* gq = g - m;
    const size_t SX = (size_t)NC * NC;
    const size_t SY = NC;

    #define DEPOSIT_ROW(base_off, rw)  do {                                   \
        float v0 = (rw) * z0;                                                 \
        float v1 = (rw) * z1;                                                 \
        float l0 = v0 * a0;                                                   \
        float l1 = fmaf(v1, a0, v0 * a1);                                     \
        float l2 = fmaf(v1, a1, v0 * a2);                                     \
        float l3 = v1 * a2;                                                   \
        red_v4p(gq + (base_off), l0, l1, l2, l3, use4);                       \
        red_v1p(g + (base_off), v0, fb);                                      \
        red_v1p(g + (base_off) + 1, v1, fb2);                                 \
    } while (0)

    DEPOSIT_ROW(0, wx0 * y0);
    if (by) DEPOSIT_ROW(SY, wx0 * y1);
    if (bx) {
        DEPOSIT_ROW(SX, wx1 * y0);
        if (by) DEPOSIT_ROW(SX + SY, wx1 * y1);
    }
    #undef DEPOSIT_ROW
}

__global__ void __launch_bounds__(256) cic_deposit_kernel(
    const float* __restrict__ pos,
    const float* __restrict__ wgt,
    float* __restrict__ grid,
    int n, int pass)
{
    int t = blockIdx.x * blockDim.x + threadIdx.x;
    int base = 4 * t;
    if (base >= n) return;

    if (base + 3 < n) {
        const float4* p4 = (const float4*)pos + 3 * (size_t)t;
        float4 A = __ldcs(p4 + 0);
        float4 B = __ldcs(p4 + 1);
        float4 C = __ldcs(p4 + 2);
        float4 W = __ldcs((const float4*)wgt + t);

        deposit_one(A.x, A.y, A.z, W.x, grid, pass);
        deposit_one(A.w, B.x, B.y, W.y, grid, pass);
        deposit_one(B.z, B.w, C.x, W.z, grid, pass);
        deposit_one(C.y, C.z, C.w, W.w, grid, pass);
    } else {
        for (int i = base; i < n; i++) {
            float px = __ldcs(pos + 3 * (size_t)i + 0);
            float py = __ldcs(pos + 3 * (size_t)i + 1);
            float pz = __ldcs(pos + 3 * (size_t)i + 2);
            float w  = __ldcs(wgt + i);
            deposit_one(px, py, pz, w, grid, pass);
        }
    }
}

extern "C" void kernel_launch(void* const* d_in, const int* in_sizes, int n_in,
                              void* d_out, int out_size) {
    const float* positions = (const float*)d_in[0];
    const float* weights   = (const float*)d_in[1];
    float* grid = (float*)d_out;

    int n_particles = in_sizes[1];  // weights element count = N

    int n4 = out_size / 4;
    zero_grid_kernel<<<(n4 + 255) / 256, 256>>>((float4*)grid, n4);

    int n_threads_total = (n_particles + 3) / 4;
    int threads = 256;
    int blocks = (n_threads_total + threads - 1) / threads;
    cic_deposit_kernel<<<blocks, threads>>>(positions, weights, grid, n_particles, 0);
    cic_deposit_kernel<<<blocks, threads>>>(positions, weights, grid, n_particles, 1);
}

// round 5
// speedup vs baseline: 1.0689x; 1.0689x over previous
#include <cuda_runtime.h>
#include <cstdint>

// CIC deposition: 10M particles -> 256^3 float grid.
// Round 5: deposit into a 2x2x2-block-permuted scratch grid so a particle's
// 8 trilinear corners collapse into 2..8 (avg 4.5) aligned v4 REDs touching
// avg 3.375 32B sectors (vs 5 before). Then de-permute into d_out.
// Permuted layout: p(x,y,z) = ((((x>>1)*128 + (y>>1))*128 + (z>>1)) << 3)
//                             + ((x&1)<<2) + ((y&1)<<1) + (z&1)

static constexpr int   NC    = 256;
static constexpr float GMINF = -10.0f;
static constexpr float DXF   = (float)(20.0 / 255.0);

__device__ float g_perm[256u * 256u * 256u];   // 64MB permuted accumulator

__global__ void zero_perm_kernel(int n4) {
    int i = blockIdx.x * blockDim.x + threadIdx.x;
    if (i < n4) ((float4*)g_perm)[i] = make_float4(0.f, 0.f, 0.f, 0.f);
}

__device__ __forceinline__ void red_v4p(float* p, float a, float b, float c, float d, int pred) {
    asm volatile(
        "{\n\t"
        ".reg .pred q;\n\t"
        "setp.ne.s32 q, %5, 0;\n\t"
        "@q red.global.add.v4.f32 [%0], {%1, %2, %3, %4};\n\t"
        "}"
        :: "l"(p), "f"(a), "f"(b), "f"(c), "f"(d), "r"(pred) : "memory");
}

__device__ __forceinline__ void deposit_one(float px, float py, float pz, float w)
{
    // Match JAX float32 arithmetic: subtract then IEEE divide
    float fx = (px - GMINF) / DXF;
    float fy = (py - GMINF) / DXF;
    float fz = (pz - GMINF) / DXF;

    float ixf = floorf(fx), iyf = floorf(fy), izf = floorf(fz);
    int cx = (int)ixf, cy = (int)iyf, cz = (int)izf;

    if ((unsigned)cx > 255u || (unsigned)cy > 255u || (unsigned)cz > 255u) return;

    float ox = fx - ixf, oy = fy - iyf, oz = fz - izf;

    // corner weight = ((w * X) * Y) * Z  (reference association)
    float wx0 = w * (1.0f - ox);
    float wx1 = w * ox;
    float fy0 = 1.0f - oy, fy1 = oy;
    float fz0 = 1.0f - oz, fz1 = oz;

    int bx = cx & 1, by = cy & 1, bz = cz & 1;
    int Yb = cy >> 1, Zb = cz >> 1;

    // per-(block-offset dy) lane weights for y-bits 0/1 inside the block
    float y00 = by ? 0.0f : fy0;   // dy=0, ybit0
    float y01 = by ? fy0  : fy1;   // dy=0, ybit1
    float y10 = fy1;               // dy=1, ybit0 (active only when by)
    float z00 = bz ? 0.0f : fz0;
    float z01 = bz ? fz0  : fz1;
    float z10 = fz1;

    int pdy = by & (cy < 255);            // block Yb+1 exists & corner kept
    int pdz = bz & (cz < 255);
    int ptx = (!bx) | (cx < 255);         // second x-target valid

    // products per (dy,dz), lane order = ybit*2 + zbit
    float tA0 = y00 * z00, tA1 = y00 * z01, tA2 = y01 * z00, tA3 = y01 * z01; // (0,0)
    float tB0 = y00 * z10,                  tB2 = y01 * z10;                   // (0,1)
    float tC0 = y10 * z00, tC1 = y10 * z01;                                    // (1,0)
    float tD0 = y10 * z10;                                                     // (1,1)

    #pragma unroll
    for (int k = 0; k < 2; k++) {
        int xc   = cx + k;
        int X    = xc >> 1;
        int half = xc & 1;
        float xw = k ? wx1 : wx0;
        int pk   = k ? ptx : 1;

        float* p00 = g_perm + (((((size_t)X << 7) | (size_t)Yb) << 7 | (size_t)Zb) << 3)
                            + ((size_t)half << 2);
        red_v4p(p00,            xw * tA0, xw * tA1, xw * tA2, xw * tA3, pk);
        red_v4p(p00 + 8,        xw * tB0, 0.0f,     xw * tB2, 0.0f,     pk & pdz);
        red_v4p(p00 + 1024,     xw * tC0, xw * tC1, 0.0f,     0.0f,     pk & pdy);
        red_v4p(p00 + 1024 + 8, xw * tD0, 0.0f,     0.0f,     0.0f,     pk & pdy & pdz);
    }
}

__global__ void __launch_bounds__(256) cic_deposit_kernel(
    const float* __restrict__ pos,
    const float* __restrict__ wgt,
    int n)
{
    int t = blockIdx.x * blockDim.x + threadIdx.x;
    int base = 4 * t;
    if (base >= n) return;

    if (base + 3 < n) {
        const float4* p4 = (const float4*)pos + 3 * (size_t)t;
        float4 A = __ldcs(p4 + 0);
        float4 B = __ldcs(p4 + 1);
        float4 C = __ldcs(p4 + 2);
        float4 W = __ldcs((const float4*)wgt + t);

        deposit_one(A.x, A.y, A.z, W.x);
        deposit_one(A.w, B.x, B.y, W.y);
        deposit_one(B.z, B.w, C.x, W.z);
        deposit_one(C.y, C.z, C.w, W.w);
    } else {
        for (int i = base; i < n; i++) {
            float ppx = __ldcs(pos + 3 * (size_t)i + 0);
            float ppy = __ldcs(pos + 3 * (size_t)i + 1);
            float ppz = __ldcs(pos + 3 * (size_t)i + 2);
            float ww  = __ldcs(wgt + i);
            deposit_one(ppx, ppy, ppz, ww);
        }
    }
}

// de-permute: out[x][y][z], one thread produces 4 consecutive z as float4
__global__ void __launch_bounds__(256) depermute_kernel(float4* __restrict__ out, int n4) {
    int t = blockIdx.x * blockDim.x + threadIdx.x;
    if (t >= n4) return;
    int z4 = t & 63;          // z block-of-4 index
    int y  = (t >> 6) & 255;
    int x  = t >> 14;
    int X = x >> 1, Y = y >> 1;
    int off = ((x & 1) << 2) | ((y & 1) << 1);
    int Z0 = z4 << 1;
    const float* b0 = g_perm + (((((size_t)X << 7) | (size_t)Y) << 7 | (size_t)Z0) << 3) + off;
    float2 a = *(const float2*)b0;         // block Z0:   z = 4*z4, 4*z4+1
    float2 b = *(const float2*)(b0 + 8);   // block Z0+1: z = 4*z4+2, 4*z4+3
    out[t] = make_float4(a.x, a.y, b.x, b.y);
}

extern "C" void kernel_launch(void* const* d_in, const int* in_sizes, int n_in,
                              void* d_out, int out_size) {
    const float* positions = (const float*)d_in[0];
    const float* weights   = (const float*)d_in[1];
    float* grid = (float*)d_out;

    int n_particles = in_sizes[1];  // weights element count = N

    int n4 = out_size / 4;          // 4194304 float4 in both perm and out
    zero_perm_kernel<<<(n4 + 255) / 256, 256>>>(n4);

    int n_threads_total = (n_particles + 3) / 4;
    int threads = 256;
    int blocks = (n_threads_total + threads - 1) / threads;
    cic_deposit_kernel<<<blocks, threads>>>(positions, weights, n_particles);

    depermute_kernel<<<(n4 + 255) / 256, 256>>>((float4*)grid, n4);
}